// round 4
// baseline (speedup 1.0000x reference)
#include <cuda_runtime.h>
#include <cuda_bf16.h>
#include <cstdint>
#include <math.h>

#define BATCH 16
#define SEQ   1024
#define EDIM  512
#define NROWS (BATCH*SEQ)
#define TOTALD ((double)BATCH*SEQ*SEQ)
#define TEMP  13.544f
#define EPSV  1e-5

// ---------------- device scratch (no allocations allowed) ------------------
__device__ __nv_bfloat16 g_hi[(size_t)NROWS * EDIM];   // 16 MB
__device__ __nv_bfloat16 g_lo[(size_t)NROWS * EDIM];   // 16 MB
__device__ float  g_sq[NROWS];
__device__ double g_sum;
__device__ double g_sumsq;
__device__ float  g_coef;

// ---------------- PTX helpers ----------------------------------------------
__device__ __forceinline__ uint32_t smem_u32(const void* p) {
    uint32_t a;
    asm("{ .reg .u64 t; cvta.to.shared.u64 t, %1; cvt.u32.u64 %0, t; }" : "=r"(a) : "l"(p));
    return a;
}
__device__ __forceinline__ void cp16(uint32_t dst, const void* src) {
    asm volatile("cp.async.cg.shared.global [%0], [%1], 16;" :: "r"(dst), "l"(src));
}
#define CP_COMMIT() asm volatile("cp.async.commit_group;" ::: "memory")
#define CP_WAIT(n)  asm volatile("cp.async.wait_group %0;" :: "n"(n) : "memory")

__device__ __forceinline__ void ldm4(uint32_t* r, uint32_t addr) {
    asm volatile("ldmatrix.sync.aligned.m8n8.x4.shared.b16 {%0,%1,%2,%3}, [%4];"
                 : "=r"(r[0]), "=r"(r[1]), "=r"(r[2]), "=r"(r[3]) : "r"(addr));
}
__device__ __forceinline__ void mma16816(float* c, const uint32_t* a,
                                         uint32_t b0, uint32_t b1) {
    asm volatile("mma.sync.aligned.m16n8k16.row.col.f32.bf16.bf16.f32 "
                 "{%0,%1,%2,%3}, {%4,%5,%6,%7}, {%8,%9}, {%0,%1,%2,%3};"
                 : "+f"(c[0]), "+f"(c[1]), "+f"(c[2]), "+f"(c[3])
                 : "r"(a[0]), "r"(a[1]), "r"(a[2]), "r"(a[3]), "r"(b0), "r"(b1));
}

// ---------------- gram geometry --------------------------------------------
#define KC        32                       // k elems per chunk (64 bytes/row)
#define NCHUNK    (EDIM / KC)              // 16
#define TROWB     80                       // padded bytes per smem tile row
#define TILE_B    (128 * TROWB)            // 10240
#define NTILES    4                        // Ahi, Alo, Bhi, Blo
#define BUF_B     (NTILES * TILE_B)        // 40960
#define NSTAGE    3
#define SM_SQA    0
#define SM_SQB    512
#define SM_RED    1024                     // 8 doubles sum
#define SM_REDQ   1088                     // 8 doubles sumsq
#define SM_TILES  2048
#define TRPAD     129
#define GRAM_SMEM (SM_TILES + NSTAGE * BUF_B)   // 124928 (> 128*129*4+2048)

// ---------------------------------------------------------------------------
// Kernel 1: fp32 -> (hi, lo) bf16 split + per-row squared norms.
// ---------------------------------------------------------------------------
__global__ __launch_bounds__(256)
void conv_kernel(const float* __restrict__ x) {
    if (blockIdx.x == 0 && threadIdx.x == 0) { g_sum = 0.0; g_sumsq = 0.0; }
    int gw   = (blockIdx.x * blockDim.x + threadIdx.x) >> 5;
    int lane = threadIdx.x & 31;
    if (gw >= NROWS) return;
    const float4* row = (const float4*)(x + (size_t)gw * EDIM);
    __nv_bfloat162* hi = (__nv_bfloat162*)(g_hi + (size_t)gw * EDIM);
    __nv_bfloat162* lo = (__nv_bfloat162*)(g_lo + (size_t)gw * EDIM);
    float s = 0.f;
    #pragma unroll
    for (int i = 0; i < 4; i++) {
        int e = lane + 32 * i;
        float4 v = row[e];
        s += v.x*v.x + v.y*v.y + v.z*v.z + v.w*v.w;
        __nv_bfloat16 hx = __float2bfloat16_rn(v.x), hy = __float2bfloat16_rn(v.y);
        __nv_bfloat16 hz = __float2bfloat16_rn(v.z), hw = __float2bfloat16_rn(v.w);
        __nv_bfloat162 h0; h0.x = hx; h0.y = hy;
        __nv_bfloat162 h1; h1.x = hz; h1.y = hw;
        __nv_bfloat162 l0, l1;
        l0.x = __float2bfloat16_rn(v.x - __bfloat162float(hx));
        l0.y = __float2bfloat16_rn(v.y - __bfloat162float(hy));
        l1.x = __float2bfloat16_rn(v.z - __bfloat162float(hz));
        l1.y = __float2bfloat16_rn(v.w - __bfloat162float(hw));
        hi[e * 2] = h0; hi[e * 2 + 1] = h1;
        lo[e * 2] = l0; lo[e * 2 + 1] = l1;
    }
    #pragma unroll
    for (int o = 16; o > 0; o >>= 1) s += __shfl_xor_sync(0xffffffffu, s, o);
    if (lane == 0) g_sq[gw] = s;
}

// ---------------------------------------------------------------------------
// Kernel 2: symmetric Gram, upper-triangle tile pairs only.
// 256 threads, 8 warps of 64x32, 3-stage cp.async, 1 sync per K-chunk.
// ---------------------------------------------------------------------------
__device__ __forceinline__ void prefetch_chunk(
    const __nv_bfloat16* Ahi, const __nv_bfloat16* Alo,
    const __nv_bfloat16* Bhi, const __nv_bfloat16* Blo,
    uint32_t sb, int buf, int kc, int tid)
{
    const __nv_bfloat16* panels[NTILES] = { Ahi, Alo, Bhi, Blo };
    int p = tid >> 6, s = tid & 63;          // 64 threads per panel
    const char* src = (const char*)panels[p] + kc * (KC * 2);
    uint32_t tb = sb + SM_TILES + buf * BUF_B + p * TILE_B;
    #pragma unroll
    for (int i = 0; i < 8; i++) {
        int idx = i * 64 + s;                // 0..511 (16B granules)
        int row = idx >> 2;
        int q   = idx & 3;
        cp16(tb + row * TROWB + q * 16,
             src + (size_t)row * (EDIM * 2) + q * 16);
    }
}

__global__ __launch_bounds__(256, 1)
void gram_tc_kernel(float* __restrict__ dout) {
    extern __shared__ char smem[];
    const uint32_t sb = smem_u32(smem);
    const int tid  = threadIdx.x;
    const int wid  = tid >> 5;
    const int lane = tid & 31;

    // decode upper-triangle tile pair
    int p = blockIdx.x, ti = 0;
    while (p >= 8 - ti) { p -= 8 - ti; ti++; }
    const int tj   = ti + p;
    const int b    = blockIdx.z;
    const int row0 = ti * 128;
    const int col0 = tj * 128;
    const int warp_m = (wid >> 2) * 64;
    const int warp_n = (wid & 3) * 32;

    const __nv_bfloat16* Ahi = g_hi + ((size_t)(b * SEQ + row0)) * EDIM;
    const __nv_bfloat16* Alo = g_lo + ((size_t)(b * SEQ + row0)) * EDIM;
    const __nv_bfloat16* Bhi = g_hi + ((size_t)(b * SEQ + col0)) * EDIM;
    const __nv_bfloat16* Blo = g_lo + ((size_t)(b * SEQ + col0)) * EDIM;

    if (tid < 128) {
        ((float*)(smem + SM_SQA))[tid] = g_sq[b * SEQ + row0 + tid];
        ((float*)(smem + SM_SQB))[tid] = g_sq[b * SEQ + col0 + tid];
    }

    float acc[4][4][4];
    #pragma unroll
    for (int mi = 0; mi < 4; mi++)
        #pragma unroll
        for (int ni = 0; ni < 4; ni++)
            #pragma unroll
            for (int k = 0; k < 4; k++) acc[mi][ni][k] = 0.f;

    const uint32_t aOff = (uint32_t)((warp_m + (lane & 15)) * TROWB + (lane >> 4) * 16);
    const uint32_t bOff = (uint32_t)((warp_n + (lane & 7) + ((lane >> 4) << 3)) * TROWB
                                     + ((lane >> 3) & 1) * 16);

    prefetch_chunk(Ahi, Alo, Bhi, Blo, sb, 0, 0, tid); CP_COMMIT();
    prefetch_chunk(Ahi, Alo, Bhi, Blo, sb, 1, 1, tid); CP_COMMIT();

    #pragma unroll 1
    for (int c = 0; c < NCHUNK; c++) {
        if (c + 1 < NCHUNK) { CP_WAIT(1); } else { CP_WAIT(0); }
        __syncthreads();   // chunk c visible; mma(c-1) finished everywhere
        if (c + 2 < NCHUNK) {
            prefetch_chunk(Ahi, Alo, Bhi, Blo, sb, (c + 2) % NSTAGE, c + 2, tid);
            CP_COMMIT();
        }
        uint32_t base = sb + SM_TILES + (c % NSTAGE) * BUF_B;
        #pragma unroll
        for (int ks = 0; ks < 2; ks++) {
            const uint32_t kb = ks * 32;
            uint32_t aH[16], aL[16], bH[8], bL[8];
            #pragma unroll
            for (int mi = 0; mi < 4; mi++) {
                ldm4(&aH[mi * 4], base + 0 * TILE_B + aOff + mi * 16 * TROWB + kb);
                ldm4(&aL[mi * 4], base + 1 * TILE_B + aOff + mi * 16 * TROWB + kb);
            }
            #pragma unroll
            for (int nj = 0; nj < 2; nj++) {
                ldm4(&bH[nj * 4], base + 2 * TILE_B + bOff + nj * 16 * TROWB + kb);
                ldm4(&bL[nj * 4], base + 3 * TILE_B + bOff + nj * 16 * TROWB + kb);
            }
            #pragma unroll
            for (int mi = 0; mi < 4; mi++)
                #pragma unroll
                for (int ni = 0; ni < 4; ni++) {
                    mma16816(acc[mi][ni], &aH[mi * 4], bH[ni * 2], bH[ni * 2 + 1]);
                    mma16816(acc[mi][ni], &aL[mi * 4], bH[ni * 2], bH[ni * 2 + 1]);
                    mma16816(acc[mi][ni], &aH[mi * 4], bL[ni * 2], bL[ni * 2 + 1]);
                }
        }
    }
    __syncthreads();   // all MMA done before smem reuse as transpose buffer

    // ---------------- epilogue -------------------------------------------
    const int g  = lane >> 2;
    const int t4 = lane & 3;
    const float* sqA = (const float*)(smem + SM_SQA);
    const float* sqB = (const float*)(smem + SM_SQB);
    float* trb = (float*)(smem + SM_TILES);
    float* Db  = dout + (size_t)b * SEQ * SEQ;
    float fsum = 0.f, fsq = 0.f;
    #pragma unroll
    for (int mi = 0; mi < 4; mi++) {
        #pragma unroll
        for (int h = 0; h < 2; h++) {
            int rl = warp_m + mi * 16 + g + h * 8;
            float sr = sqA[rl];
            float* rp = Db + (size_t)(row0 + rl) * SEQ + col0;
            #pragma unroll
            for (int ni = 0; ni < 4; ni++) {
                int cl = warp_n + ni * 8 + t4 * 2;
                float d0 = fmaxf(sr + sqB[cl]     - 2.f * acc[mi][ni][2 * h],     0.f);
                float d1 = fmaxf(sr + sqB[cl + 1] - 2.f * acc[mi][ni][2 * h + 1], 0.f);
                fsum += d0 + d1;
                fsq  += d0 * d0 + d1 * d1;
                float2 o; o.x = d0; o.y = d1;
                *(float2*)(rp + cl) = o;
                trb[rl * TRPAD + cl]     = d0;
                trb[rl * TRPAD + cl + 1] = d1;
            }
        }
    }

    if (ti != tj) {
        // transposed copy to tile (tj, ti)
        __syncthreads();
        int cc = tid >> 1;
        int rh = (tid & 1) * 64;
        float* op = Db + (size_t)(col0 + cc) * SEQ + row0 + rh;
        #pragma unroll
        for (int i = 0; i < 64; i += 4) {
            float4 v;
            v.x = trb[(rh + i + 0) * TRPAD + cc];
            v.y = trb[(rh + i + 1) * TRPAD + cc];
            v.z = trb[(rh + i + 2) * TRPAD + cc];
            v.w = trb[(rh + i + 3) * TRPAD + cc];
            *(float4*)(op + i) = v;
        }
        fsum *= 2.f; fsq *= 2.f;   // off-diag tile counts twice in stats
    }

    // stats reduction
    #pragma unroll
    for (int o = 16; o > 0; o >>= 1) {
        fsum += __shfl_xor_sync(0xffffffffu, fsum, o);
        fsq  += __shfl_xor_sync(0xffffffffu, fsq,  o);
    }
    if (lane == 0) {
        ((double*)(smem + SM_RED))[wid]  = (double)fsum;
        ((double*)(smem + SM_REDQ))[wid] = (double)fsq;
    }
    __syncthreads();
    if (tid == 0) {
        double s = 0.0, q = 0.0;
        #pragma unroll
        for (int k = 0; k < 8; k++) {
            s += ((double*)(smem + SM_RED))[k];
            q += ((double*)(smem + SM_REDQ))[k];
        }
        atomicAdd(&g_sum, s);
        atomicAdd(&g_sumsq, q);
    }
}

// ---------------------------------------------------------------------------
__global__ void finalize_kernel(const float* __restrict__ gamma) {
    double mean = g_sum / TOTALD;
    double var  = g_sumsq / TOTALD - mean * mean;
    double rstd = 1.0 / sqrt(var + EPSV);
    g_coef = (float)(-(double)gamma[0] * rstd / (double)TEMP);
}

// ---------------------------------------------------------------------------
__global__ __launch_bounds__(256)
void softmax_kernel(float* __restrict__ dout) {
    __shared__ float red[8];
    size_t base = (size_t)blockIdx.x * SEQ;
    float coef = g_coef;
    int tid = threadIdx.x;

    float4 v = *(float4*)(dout + base + tid * 4);
    float t0 = coef * v.x, t1 = coef * v.y, t2 = coef * v.z, t3 = coef * v.w;

    float m = fmaxf(fmaxf(t0, t1), fmaxf(t2, t3));
    #pragma unroll
    for (int o = 16; o > 0; o >>= 1) m = fmaxf(m, __shfl_xor_sync(0xffffffffu, m, o));
    if ((tid & 31) == 0) red[tid >> 5] = m;
    __syncthreads();
    float bm = red[0];
    #pragma unroll
    for (int i = 1; i < 8; i++) bm = fmaxf(bm, red[i]);

    float e0 = __expf(t0 - bm), e1 = __expf(t1 - bm);
    float e2 = __expf(t2 - bm), e3 = __expf(t3 - bm);
    float s = e0 + e1 + e2 + e3;
    #pragma unroll
    for (int o = 16; o > 0; o >>= 1) s += __shfl_xor_sync(0xffffffffu, s, o);
    __syncthreads();
    if ((tid & 31) == 0) red[tid >> 5] = s;
    __syncthreads();
    float bs = 0.f;
    #pragma unroll
    for (int i = 0; i < 8; i++) bs += red[i];
    float inv = 1.f / bs;

    *(float4*)(dout + base + tid * 4) =
        make_float4(e0 * inv, e1 * inv, e2 * inv, e3 * inv);
}

// ---------------------------------------------------------------------------
extern "C" void kernel_launch(void* const* d_in, const int* in_sizes, int n_in,
                              void* d_out, int out_size) {
    const float* x     = (const float*)d_in[0];
    const float* gamma = (const float*)d_in[1];
    float* out = (float*)d_out;

    cudaFuncSetAttribute(gram_tc_kernel,
                         cudaFuncAttributeMaxDynamicSharedMemorySize, GRAM_SMEM);

    conv_kernel<<<NROWS * 32 / 256, 256>>>(x);
    dim3 grid(36, 1, BATCH);
    gram_tc_kernel<<<grid, 256, GRAM_SMEM>>>(out);
    finalize_kernel<<<1, 1>>>(gamma);
    softmax_kernel<<<NROWS, 256>>>(out);
}

// round 5
// speedup vs baseline: 1.6406x; 1.6406x over previous
#include <cuda_runtime.h>
#include <cuda_bf16.h>
#include <cstdint>
#include <math.h>

#define BATCH 16
#define SEQ   1024
#define EDIM  512
#define NROWS (BATCH*SEQ)
#define TOTALD ((double)BATCH*SEQ*SEQ)
#define TEMP  13.544f
#define EPSV  1e-5

// ---------------- device scratch (no allocations allowed) ------------------
__device__ __nv_bfloat16 g_hi[(size_t)NROWS * EDIM];   // 16 MB
__device__ __nv_bfloat16 g_lo[(size_t)NROWS * EDIM];   // 16 MB
__device__ float  g_sq[NROWS];
__device__ double g_sum;
__device__ double g_sumsq;
__device__ float  g_coef;

// ---------------- PTX helpers ----------------------------------------------
__device__ __forceinline__ uint32_t smem_u32(const void* p) {
    uint32_t a;
    asm("{ .reg .u64 t; cvta.to.shared.u64 t, %1; cvt.u32.u64 %0, t; }" : "=r"(a) : "l"(p));
    return a;
}
__device__ __forceinline__ void cp16(uint32_t dst, const void* src) {
    asm volatile("cp.async.cg.shared.global [%0], [%1], 16;" :: "r"(dst), "l"(src));
}
#define CP_COMMIT() asm volatile("cp.async.commit_group;" ::: "memory")
#define CP_WAIT(n)  asm volatile("cp.async.wait_group %0;" :: "n"(n) : "memory")

__device__ __forceinline__ void ldm4(uint32_t* r, uint32_t addr) {
    asm volatile("ldmatrix.sync.aligned.m8n8.x4.shared.b16 {%0,%1,%2,%3}, [%4];"
                 : "=r"(r[0]), "=r"(r[1]), "=r"(r[2]), "=r"(r[3]) : "r"(addr));
}
__device__ __forceinline__ void mma16816(float* c, const uint32_t* a,
                                         uint32_t b0, uint32_t b1) {
    asm volatile("mma.sync.aligned.m16n8k16.row.col.f32.bf16.bf16.f32 "
                 "{%0,%1,%2,%3}, {%4,%5,%6,%7}, {%8,%9}, {%0,%1,%2,%3};"
                 : "+f"(c[0]), "+f"(c[1]), "+f"(c[2]), "+f"(c[3])
                 : "r"(a[0]), "r"(a[1]), "r"(a[2]), "r"(a[3]), "r"(b0), "r"(b1));
}

// ---------------- gram geometry (identical to round-3 winner) --------------
#define KC        32
#define NCHUNK    (EDIM / KC)              // 16
#define TROWB     80
#define TILE_B    (128 * TROWB)            // 10240
#define NTILES    4                        // Ahi, Alo, Bhi, Blo
#define BUF_B     (NTILES * TILE_B)        // 40960
#define SM_SQA    0
#define SM_SQB    512
#define SM_RED    1024
#define SM_REDQ   1056
#define SM_TILES  2048
#define TRPAD     129                      // transpose staging: 128*129*4 = 66048 <= 2*BUF_B
#define GRAM_SMEM (SM_TILES + 2 * BUF_B)   // 83968 -> 2 CTAs/SM

// ---------------------------------------------------------------------------
// Kernel 1: fp32 -> (hi, lo) bf16 split + per-row squared norms.
// ---------------------------------------------------------------------------
__global__ __launch_bounds__(256)
void conv_kernel(const float* __restrict__ x) {
    if (blockIdx.x == 0 && threadIdx.x == 0) { g_sum = 0.0; g_sumsq = 0.0; }
    int gw   = (blockIdx.x * blockDim.x + threadIdx.x) >> 5;
    int lane = threadIdx.x & 31;
    if (gw >= NROWS) return;
    const float4* row = (const float4*)(x + (size_t)gw * EDIM);
    __nv_bfloat162* hi = (__nv_bfloat162*)(g_hi + (size_t)gw * EDIM);
    __nv_bfloat162* lo = (__nv_bfloat162*)(g_lo + (size_t)gw * EDIM);
    float s = 0.f;
    #pragma unroll
    for (int i = 0; i < 4; i++) {
        int e = lane + 32 * i;
        float4 v = row[e];
        s += v.x*v.x + v.y*v.y + v.z*v.z + v.w*v.w;
        __nv_bfloat16 hx = __float2bfloat16_rn(v.x), hy = __float2bfloat16_rn(v.y);
        __nv_bfloat16 hz = __float2bfloat16_rn(v.z), hw = __float2bfloat16_rn(v.w);
        __nv_bfloat162 h0; h0.x = hx; h0.y = hy;
        __nv_bfloat162 h1; h1.x = hz; h1.y = hw;
        __nv_bfloat162 l0, l1;
        l0.x = __float2bfloat16_rn(v.x - __bfloat162float(hx));
        l0.y = __float2bfloat16_rn(v.y - __bfloat162float(hy));
        l1.x = __float2bfloat16_rn(v.z - __bfloat162float(hz));
        l1.y = __float2bfloat16_rn(v.w - __bfloat162float(hw));
        hi[e * 2] = h0; hi[e * 2 + 1] = h1;
        lo[e * 2] = l0; lo[e * 2 + 1] = l1;
    }
    #pragma unroll
    for (int o = 16; o > 0; o >>= 1) s += __shfl_xor_sync(0xffffffffu, s, o);
    if (lane == 0) g_sq[gw] = s;
}

// ---------------------------------------------------------------------------
// Kernel 2: symmetric Gram via round-3 mainloop. Upper-triangle tile pairs,
// 128 threads / 4 warps of 64x64, 2-stage cp.async, 2 CTAs/SM.
// ---------------------------------------------------------------------------
__device__ __forceinline__ void prefetch_chunk(
    const __nv_bfloat16* Ahi, const __nv_bfloat16* Alo,
    const __nv_bfloat16* Bhi, const __nv_bfloat16* Blo,
    uint32_t sb, int buf, int kc, int tid)
{
    const __nv_bfloat16* panels[NTILES] = { Ahi, Alo, Bhi, Blo };
    int w = tid >> 5, lane = tid & 31;
    const char* src = (const char*)panels[w] + kc * (KC * 2);
    uint32_t tb = sb + SM_TILES + buf * BUF_B + w * TILE_B;
    #pragma unroll
    for (int i = 0; i < 16; i++) {
        int idx = i * 32 + lane;
        int row = idx >> 2;
        int q   = idx & 3;
        cp16(tb + row * TROWB + q * 16,
             src + (size_t)row * (EDIM * 2) + q * 16);
    }
}

__global__ __launch_bounds__(128, 2)
void gram_tc_kernel(float* __restrict__ dout) {
    extern __shared__ char smem[];
    const uint32_t sb = smem_u32(smem);
    const int tid  = threadIdx.x;
    const int wid  = tid >> 5;
    const int lane = tid & 31;

    // decode upper-triangle tile pair (8x8 tiles, 36 pairs)
    int p = blockIdx.x, ti = 0;
    while (p >= 8 - ti) { p -= 8 - ti; ti++; }
    const int tj   = ti + p;
    const int b    = blockIdx.z;
    const int row0 = ti * 128;
    const int col0 = tj * 128;
    const int warp_m = (wid >> 1) * 64;
    const int warp_n = (wid & 1) * 64;

    const __nv_bfloat16* Ahi = g_hi + ((size_t)(b * SEQ + row0)) * EDIM;
    const __nv_bfloat16* Alo = g_lo + ((size_t)(b * SEQ + row0)) * EDIM;
    const __nv_bfloat16* Bhi = g_hi + ((size_t)(b * SEQ + col0)) * EDIM;
    const __nv_bfloat16* Blo = g_lo + ((size_t)(b * SEQ + col0)) * EDIM;

    if (tid < 128) {
        ((float*)(smem + SM_SQA))[tid] = g_sq[b * SEQ + row0 + tid];
        ((float*)(smem + SM_SQB))[tid] = g_sq[b * SEQ + col0 + tid];
    }

    float acc[4][8][4];
    #pragma unroll
    for (int mi = 0; mi < 4; mi++)
        #pragma unroll
        for (int ni = 0; ni < 8; ni++)
            #pragma unroll
            for (int k = 0; k < 4; k++) acc[mi][ni][k] = 0.f;

    const uint32_t aOff = (uint32_t)((warp_m + (lane & 15)) * TROWB + (lane >> 4) * 16);
    const uint32_t bOff = (uint32_t)((warp_n + (lane & 7) + ((lane >> 4) << 3)) * TROWB
                                     + ((lane >> 3) & 1) * 16);

    prefetch_chunk(Ahi, Alo, Bhi, Blo, sb, 0, 0, tid);
    CP_COMMIT();

    #pragma unroll 1
    for (int c = 0; c < NCHUNK; c++) {
        if (c + 1 < NCHUNK) {
            prefetch_chunk(Ahi, Alo, Bhi, Blo, sb, (c + 1) & 1, c + 1, tid);
            CP_COMMIT();
            CP_WAIT(1);
        } else {
            CP_WAIT(0);
        }
        __syncthreads();

        uint32_t base = sb + SM_TILES + (c & 1) * BUF_B;
        #pragma unroll
        for (int ks = 0; ks < 2; ks++) {
            const uint32_t kb = ks * 32;
            uint32_t aH[16], aL[16], bb[16];
            #pragma unroll
            for (int mi = 0; mi < 4; mi++) {
                ldm4(&aH[mi * 4], base + 0 * TILE_B + aOff + mi * 16 * TROWB + kb);
                ldm4(&aL[mi * 4], base + 1 * TILE_B + aOff + mi * 16 * TROWB + kb);
            }
            #pragma unroll
            for (int nj = 0; nj < 4; nj++)
                ldm4(&bb[nj * 4], base + 2 * TILE_B + bOff + nj * 16 * TROWB + kb);
            #pragma unroll
            for (int mi = 0; mi < 4; mi++)
                #pragma unroll
                for (int ni = 0; ni < 8; ni++) {
                    mma16816(acc[mi][ni], &aH[mi * 4], bb[ni * 2], bb[ni * 2 + 1]);
                    mma16816(acc[mi][ni], &aL[mi * 4], bb[ni * 2], bb[ni * 2 + 1]);
                }
            #pragma unroll
            for (int nj = 0; nj < 4; nj++)
                ldm4(&bb[nj * 4], base + 3 * TILE_B + bOff + nj * 16 * TROWB + kb);
            #pragma unroll
            for (int mi = 0; mi < 4; mi++)
                #pragma unroll
                for (int ni = 0; ni < 8; ni++)
                    mma16816(acc[mi][ni], &aH[mi * 4], bb[ni * 2], bb[ni * 2 + 1]);
        }
        __syncthreads();
    }

    // ---------------- epilogue -------------------------------------------
    const int g  = lane >> 2;
    const int t4 = lane & 3;
    const float* sqA = (const float*)(smem + SM_SQA);
    const float* sqB = (const float*)(smem + SM_SQB);
    float* trb = (float*)(smem + SM_TILES);
    float* Db  = dout + (size_t)b * SEQ * SEQ;
    float fsum = 0.f, fsq = 0.f;
    #pragma unroll
    for (int mi = 0; mi < 4; mi++) {
        #pragma unroll
        for (int h = 0; h < 2; h++) {
            int rl = warp_m + mi * 16 + g + h * 8;
            float sr = sqA[rl];
            float* rp = Db + (size_t)(row0 + rl) * SEQ + col0;
            #pragma unroll
            for (int ni = 0; ni < 8; ni++) {
                int cl = warp_n + ni * 8 + t4 * 2;
                float d0 = fmaxf(sr + sqB[cl]     - 2.f * acc[mi][ni][2 * h],     0.f);
                float d1 = fmaxf(sr + sqB[cl + 1] - 2.f * acc[mi][ni][2 * h + 1], 0.f);
                fsum += d0 + d1;
                fsq  += d0 * d0 + d1 * d1;
                float2 o; o.x = d0; o.y = d1;
                *(float2*)(rp + cl) = o;
                trb[rl * TRPAD + cl]     = d0;
                trb[rl * TRPAD + cl + 1] = d1;
            }
        }
    }

    if (ti != tj) {
        __syncthreads();   // trb fully written
        int cc = tid;      // one column per thread (0..127)
        float* op = Db + (size_t)(col0 + cc) * SEQ + row0;
        #pragma unroll
        for (int i = 0; i < 128; i += 4) {
            float4 v;
            v.x = trb[(i + 0) * TRPAD + cc];
            v.y = trb[(i + 1) * TRPAD + cc];
            v.z = trb[(i + 2) * TRPAD + cc];
            v.w = trb[(i + 3) * TRPAD + cc];
            *(float4*)(op + i) = v;
        }
        fsum *= 2.f; fsq *= 2.f;   // off-diag tile counts twice
    }

    // stats reduction
    #pragma unroll
    for (int o = 16; o > 0; o >>= 1) {
        fsum += __shfl_xor_sync(0xffffffffu, fsum, o);
        fsq  += __shfl_xor_sync(0xffffffffu, fsq,  o);
    }
    if (lane == 0) {
        ((double*)(smem + SM_RED))[wid]  = (double)fsum;
        ((double*)(smem + SM_REDQ))[wid] = (double)fsq;
    }
    __syncthreads();
    if (tid == 0) {
        double s = 0.0, q = 0.0;
        #pragma unroll
        for (int k = 0; k < 4; k++) {
            s += ((double*)(smem + SM_RED))[k];
            q += ((double*)(smem + SM_REDQ))[k];
        }
        atomicAdd(&g_sum, s);
        atomicAdd(&g_sumsq, q);
    }
}

// ---------------------------------------------------------------------------
__global__ void finalize_kernel(const float* __restrict__ gamma) {
    double mean = g_sum / TOTALD;
    double var  = g_sumsq / TOTALD - mean * mean;
    double rstd = 1.0 / sqrt(var + EPSV);
    g_coef = (float)(-(double)gamma[0] * rstd / (double)TEMP);
}

// ---------------------------------------------------------------------------
__global__ __launch_bounds__(256)
void softmax_kernel(float* __restrict__ dout) {
    __shared__ float red[8];
    size_t base = (size_t)blockIdx.x * SEQ;
    float coef = g_coef;
    int tid = threadIdx.x;

    float4 v = *(float4*)(dout + base + tid * 4);
    float t0 = coef * v.x, t1 = coef * v.y, t2 = coef * v.z, t3 = coef * v.w;

    float m = fmaxf(fmaxf(t0, t1), fmaxf(t2, t3));
    #pragma unroll
    for (int o = 16; o > 0; o >>= 1) m = fmaxf(m, __shfl_xor_sync(0xffffffffu, m, o));
    if ((tid & 31) == 0) red[tid >> 5] = m;
    __syncthreads();
    float bm = red[0];
    #pragma unroll
    for (int i = 1; i < 8; i++) bm = fmaxf(bm, red[i]);

    float e0 = __expf(t0 - bm), e1 = __expf(t1 - bm);
    float e2 = __expf(t2 - bm), e3 = __expf(t3 - bm);
    float s = e0 + e1 + e2 + e3;
    #pragma unroll
    for (int o = 16; o > 0; o >>= 1) s += __shfl_xor_sync(0xffffffffu, s, o);
    __syncthreads();
    if ((tid & 31) == 0) red[tid >> 5] = s;
    __syncthreads();
    float bs = 0.f;
    #pragma unroll
    for (int i = 0; i < 8; i++) bs += red[i];
    float inv = 1.f / bs;

    *(float4*)(dout + base + tid * 4) =
        make_float4(e0 * inv, e1 * inv, e2 * inv, e3 * inv);
}

// ---------------------------------------------------------------------------
extern "C" void kernel_launch(void* const* d_in, const int* in_sizes, int n_in,
                              void* d_out, int out_size) {
    const float* x     = (const float*)d_in[0];
    const float* gamma = (const float*)d_in[1];
    float* out = (float*)d_out;

    cudaFuncSetAttribute(gram_tc_kernel,
                         cudaFuncAttributeMaxDynamicSharedMemorySize, GRAM_SMEM);

    conv_kernel<<<NROWS * 32 / 256, 256>>>(x);
    dim3 grid(36, 1, BATCH);
    gram_tc_kernel<<<grid, 128, GRAM_SMEM>>>(out);
    finalize_kernel<<<1, 1>>>(gamma);
    softmax_kernel<<<NROWS, 256>>>(out);
}

// round 6
// speedup vs baseline: 3.0317x; 1.8479x over previous
#include <cuda_runtime.h>
#include <cuda_fp16.h>
#include <cstdint>
#include <math.h>

#define BATCH 16
#define SEQ   1024
#define EDIM  512
#define NROWS (BATCH*SEQ)
#define TOTALD ((double)BATCH*SEQ*SEQ)
#define TEMP  13.544f
#define EPSV  1e-5

// ---------------- device scratch (no allocations allowed) ------------------
__device__ __half g_h[(size_t)NROWS * EDIM];   // 16 MB fp16 copy of x
__device__ float  g_sq[NROWS];
__device__ double g_sum;
__device__ double g_sumsq;
__device__ float  g_coef;

// ---------------- PTX helpers ----------------------------------------------
__device__ __forceinline__ uint32_t smem_u32(const void* p) {
    uint32_t a;
    asm("{ .reg .u64 t; cvta.to.shared.u64 t, %1; cvt.u32.u64 %0, t; }" : "=r"(a) : "l"(p));
    return a;
}
__device__ __forceinline__ void cp16(uint32_t dst, const void* src) {
    asm volatile("cp.async.cg.shared.global [%0], [%1], 16;" :: "r"(dst), "l"(src));
}
#define CP_COMMIT() asm volatile("cp.async.commit_group;" ::: "memory")
#define CP_WAIT(n)  asm volatile("cp.async.wait_group %0;" :: "n"(n) : "memory")

__device__ __forceinline__ void ldm4(uint32_t* r, uint32_t addr) {
    asm volatile("ldmatrix.sync.aligned.m8n8.x4.shared.b16 {%0,%1,%2,%3}, [%4];"
                 : "=r"(r[0]), "=r"(r[1]), "=r"(r[2]), "=r"(r[3]) : "r"(addr));
}
__device__ __forceinline__ void mma16816(float* c, const uint32_t* a,
                                         uint32_t b0, uint32_t b1) {
    asm volatile("mma.sync.aligned.m16n8k16.row.col.f32.f16.f16.f32 "
                 "{%0,%1,%2,%3}, {%4,%5,%6,%7}, {%8,%9}, {%0,%1,%2,%3};"
                 : "+f"(c[0]), "+f"(c[1]), "+f"(c[2]), "+f"(c[3])
                 : "r"(a[0]), "r"(a[1]), "r"(a[2]), "r"(a[3]), "r"(b0), "r"(b1));
}

// ---------------- gram geometry --------------------------------------------
#define KC        32
#define NCHUNK    (EDIM / KC)              // 16
#define TROWB     80                       // 64B data + 16B pad
#define TILE_B    (128 * TROWB)            // 10240
#define NTILES    2                        // A, B
#define BUF_B     (NTILES * TILE_B)        // 20480
#define SM_SQA    0
#define SM_SQB    512
#define SM_RED    1024
#define SM_REDQ   1056
#define SM_TILES  2048
#define TRPAD     129                      // 128*129*4 = 66048 B staging
#define GRAM_SMEM (SM_TILES + 128 * TRPAD * 4)   // 68096 >= 2048 + 2*BUF_B

// ---------------------------------------------------------------------------
// Kernel 1: fp32 -> fp16 + per-row squared norms (fp32).
// ---------------------------------------------------------------------------
__global__ __launch_bounds__(256)
void conv_kernel(const float* __restrict__ x) {
    if (blockIdx.x == 0 && threadIdx.x == 0) { g_sum = 0.0; g_sumsq = 0.0; }
    int gw   = (blockIdx.x * blockDim.x + threadIdx.x) >> 5;
    int lane = threadIdx.x & 31;
    if (gw >= NROWS) return;
    const float4* row = (const float4*)(x + (size_t)gw * EDIM);
    __half2* hp = (__half2*)(g_h + (size_t)gw * EDIM);
    float s = 0.f;
    #pragma unroll
    for (int i = 0; i < 4; i++) {
        int e = lane + 32 * i;
        float4 v = row[e];
        s += v.x*v.x + v.y*v.y + v.z*v.z + v.w*v.w;
        hp[e * 2]     = __floats2half2_rn(v.x, v.y);
        hp[e * 2 + 1] = __floats2half2_rn(v.z, v.w);
    }
    #pragma unroll
    for (int o = 16; o > 0; o >>= 1) s += __shfl_xor_sync(0xffffffffu, s, o);
    if (lane == 0) g_sq[gw] = s;
}

// ---------------------------------------------------------------------------
// Kernel 2: symmetric fp16 Gram, upper-triangle tile pairs.
// 128 threads / 4 warps of 64x64, 2-stage cp.async, 2+ CTAs/SM.
// ---------------------------------------------------------------------------
__device__ __forceinline__ void prefetch_chunk(
    const __half* A, const __half* B, uint32_t sb, int buf, int kc, int tid)
{
    const __half* panels[NTILES] = { A, B };
    int p = tid >> 6, s = tid & 63;          // 64 threads per panel
    const char* src = (const char*)panels[p] + kc * (KC * 2);
    uint32_t tb = sb + SM_TILES + buf * BUF_B + p * TILE_B;
    #pragma unroll
    for (int i = 0; i < 8; i++) {
        int idx = i * 64 + s;                // 0..511 (16B granules)
        int row = idx >> 2;
        int q   = idx & 3;
        cp16(tb + row * TROWB + q * 16,
             src + (size_t)row * (EDIM * 2) + q * 16);
    }
}

__global__ __launch_bounds__(128, 2)
void gram_tc_kernel(float* __restrict__ dout) {
    extern __shared__ char smem[];
    const uint32_t sb = smem_u32(smem);
    const int tid  = threadIdx.x;
    const int wid  = tid >> 5;
    const int lane = tid & 31;

    // decode upper-triangle tile pair (8x8 tiles, 36 pairs)
    int p = blockIdx.x, ti = 0;
    while (p >= 8 - ti) { p -= 8 - ti; ti++; }
    const int tj   = ti + p;
    const int b    = blockIdx.z;
    const int row0 = ti * 128;
    const int col0 = tj * 128;
    const int warp_m = (wid >> 1) * 64;
    const int warp_n = (wid & 1) * 64;

    const __half* A = g_h + ((size_t)(b * SEQ + row0)) * EDIM;
    const __half* B = g_h + ((size_t)(b * SEQ + col0)) * EDIM;

    if (tid < 128) {
        ((float*)(smem + SM_SQA))[tid] = g_sq[b * SEQ + row0 + tid];
        ((float*)(smem + SM_SQB))[tid] = g_sq[b * SEQ + col0 + tid];
    }

    float acc[4][8][4];
    #pragma unroll
    for (int mi = 0; mi < 4; mi++)
        #pragma unroll
        for (int ni = 0; ni < 8; ni++)
            #pragma unroll
            for (int k = 0; k < 4; k++) acc[mi][ni][k] = 0.f;

    const uint32_t aOff = (uint32_t)((warp_m + (lane & 15)) * TROWB + (lane >> 4) * 16);
    const uint32_t bOff = (uint32_t)((warp_n + (lane & 7) + ((lane >> 4) << 3)) * TROWB
                                     + ((lane >> 3) & 1) * 16);

    prefetch_chunk(A, B, sb, 0, 0, tid);
    CP_COMMIT();

    #pragma unroll 1
    for (int c = 0; c < NCHUNK; c++) {
        if (c + 1 < NCHUNK) {
            prefetch_chunk(A, B, sb, (c + 1) & 1, c + 1, tid);
            CP_COMMIT();
            CP_WAIT(1);
        } else {
            CP_WAIT(0);
        }
        __syncthreads();

        uint32_t base = sb + SM_TILES + (c & 1) * BUF_B;
        #pragma unroll
        for (int ks = 0; ks < 2; ks++) {
            const uint32_t kb = ks * 32;
            uint32_t aF[16], bb[16];
            #pragma unroll
            for (int mi = 0; mi < 4; mi++)
                ldm4(&aF[mi * 4], base + 0 * TILE_B + aOff + mi * 16 * TROWB + kb);
            #pragma unroll
            for (int nj = 0; nj < 4; nj++)
                ldm4(&bb[nj * 4], base + 1 * TILE_B + bOff + nj * 16 * TROWB + kb);
            #pragma unroll
            for (int mi = 0; mi < 4; mi++)
                #pragma unroll
                for (int ni = 0; ni < 8; ni++)
                    mma16816(acc[mi][ni], &aF[mi * 4], bb[ni * 2], bb[ni * 2 + 1]);
        }
        __syncthreads();
    }

    // ---------------- epilogue -------------------------------------------
    const int g  = lane >> 2;
    const int t4 = lane & 3;
    const float* sqA = (const float*)(smem + SM_SQA);
    const float* sqB = (const float*)(smem + SM_SQB);
    float* trb = (float*)(smem + SM_TILES);
    float* Db  = dout + (size_t)b * SEQ * SEQ;
    const bool diag = (ti == tj);
    float fsum = 0.f, fsq = 0.f;
    #pragma unroll
    for (int mi = 0; mi < 4; mi++) {
        #pragma unroll
        for (int h = 0; h < 2; h++) {
            int rl = warp_m + mi * 16 + g + h * 8;
            float sr = sqA[rl];
            float* rp = Db + (size_t)(row0 + rl) * SEQ + col0;
            #pragma unroll
            for (int ni = 0; ni < 8; ni++) {
                int cl = warp_n + ni * 8 + t4 * 2;
                float d0 = fmaxf(sr + sqB[cl]     - 2.f * acc[mi][ni][2 * h],     0.f);
                float d1 = fmaxf(sr + sqB[cl + 1] - 2.f * acc[mi][ni][2 * h + 1], 0.f);
                if (diag) {                    // exact-zero self distance
                    if (rl == cl)     d0 = 0.f;
                    if (rl == cl + 1) d1 = 0.f;
                }
                fsum += d0 + d1;
                fsq  += d0 * d0 + d1 * d1;
                float2 o; o.x = d0; o.y = d1;
                *(float2*)(rp + cl) = o;
                trb[rl * TRPAD + cl]     = d0;
                trb[rl * TRPAD + cl + 1] = d1;
            }
        }
    }

    if (!diag) {
        __syncthreads();   // trb fully written
        int cc = tid;
        float* op = Db + (size_t)(col0 + cc) * SEQ + row0;
        #pragma unroll
        for (int i = 0; i < 128; i += 4) {
            float4 v;
            v.x = trb[(i + 0) * TRPAD + cc];
            v.y = trb[(i + 1) * TRPAD + cc];
            v.z = trb[(i + 2) * TRPAD + cc];
            v.w = trb[(i + 3) * TRPAD + cc];
            *(float4*)(op + i) = v;
        }
        fsum *= 2.f; fsq *= 2.f;
    }

    // stats reduction
    #pragma unroll
    for (int o = 16; o > 0; o >>= 1) {
        fsum += __shfl_xor_sync(0xffffffffu, fsum, o);
        fsq  += __shfl_xor_sync(0xffffffffu, fsq,  o);
    }
    if (lane == 0) {
        ((double*)(smem + SM_RED))[wid]  = (double)fsum;
        ((double*)(smem + SM_REDQ))[wid] = (double)fsq;
    }
    __syncthreads();
    if (tid == 0) {
        double s = 0.0, q = 0.0;
        #pragma unroll
        for (int k = 0; k < 4; k++) {
            s += ((double*)(smem + SM_RED))[k];
            q += ((double*)(smem + SM_REDQ))[k];
        }
        atomicAdd(&g_sum, s);
        atomicAdd(&g_sumsq, q);
    }
}

// ---------------------------------------------------------------------------
__global__ void finalize_kernel(const float* __restrict__ gamma) {
    double mean = g_sum / TOTALD;
    double var  = g_sumsq / TOTALD - mean * mean;
    double rstd = 1.0 / sqrt(var + EPSV);
    g_coef = (float)(-(double)gamma[0] * rstd / (double)TEMP);
}

// ---------------------------------------------------------------------------
// Kernel 4: warp-per-row softmax (8 rows per 256-thread block), in place.
// ---------------------------------------------------------------------------
__global__ __launch_bounds__(256)
void softmax_kernel(float* __restrict__ dout) {
    const int wid  = threadIdx.x >> 5;
    const int lane = threadIdx.x & 31;
    const size_t row = (size_t)blockIdx.x * 8 + wid;
    float4* rp = (float4*)(dout + row * SEQ);
    const float coef = g_coef;

    float4 v[8];
    #pragma unroll
    for (int i = 0; i < 8; i++) v[i] = rp[lane + 32 * i];

    float m = -1e30f;
    #pragma unroll
    for (int i = 0; i < 8; i++) {
        v[i].x *= coef; v[i].y *= coef; v[i].z *= coef; v[i].w *= coef;
        m = fmaxf(m, fmaxf(fmaxf(v[i].x, v[i].y), fmaxf(v[i].z, v[i].w)));
    }
    #pragma unroll
    for (int o = 16; o > 0; o >>= 1) m = fmaxf(m, __shfl_xor_sync(0xffffffffu, m, o));

    float s = 0.f;
    #pragma unroll
    for (int i = 0; i < 8; i++) {
        v[i].x = __expf(v[i].x - m); v[i].y = __expf(v[i].y - m);
        v[i].z = __expf(v[i].z - m); v[i].w = __expf(v[i].w - m);
        s += (v[i].x + v[i].y) + (v[i].z + v[i].w);
    }
    #pragma unroll
    for (int o = 16; o > 0; o >>= 1) s += __shfl_xor_sync(0xffffffffu, s, o);
    const float inv = 1.f / s;

    #pragma unroll
    for (int i = 0; i < 8; i++) {
        v[i].x *= inv; v[i].y *= inv; v[i].z *= inv; v[i].w *= inv;
        rp[lane + 32 * i] = v[i];
    }
}

// ---------------------------------------------------------------------------
extern "C" void kernel_launch(void* const* d_in, const int* in_sizes, int n_in,
                              void* d_out, int out_size) {
    const float* x     = (const float*)d_in[0];
    const float* gamma = (const float*)d_in[1];
    float* out = (float*)d_out;

    cudaFuncSetAttribute(gram_tc_kernel,
                         cudaFuncAttributeMaxDynamicSharedMemorySize, GRAM_SMEM);

    conv_kernel<<<NROWS * 32 / 256, 256>>>(x);
    dim3 grid(36, 1, BATCH);
    gram_tc_kernel<<<grid, 128, GRAM_SMEM>>>(out);
    finalize_kernel<<<1, 1>>>(gamma);
    softmax_kernel<<<NROWS / 8, 256>>>(out);
}